// round 13
// baseline (speedup 1.0000x reference)
#include <cuda_runtime.h>
#include <math.h>

#define T_STEPS 512
#define BATCH   64
#define INDIM   1024
#define HDIM    1024
#define BH      (BATCH * HDIM)      // 65536
#define NCTA    128
#define NTHR    512

typedef unsigned long long ull;

// ---------------- packed f32x2 helpers ----------------
__device__ __forceinline__ ull fma2(ull a, ull b, ull c) {
    ull d; asm("fma.rn.f32x2 %0, %1, %2, %3;" : "=l"(d) : "l"(a), "l"(b), "l"(c));
    return d;
}
__device__ __forceinline__ ull add2(ull a, ull b) {
    ull d; asm("add.rn.f32x2 %0, %1, %2;" : "=l"(d) : "l"(a), "l"(b));
    return d;
}
__device__ __forceinline__ ull pack2(float x, float y) {
    ull d; asm("mov.b64 %0, {%1, %2};" : "=l"(d) : "f"(x), "f"(y));
    return d;
}
__device__ __forceinline__ float2 unpack2(ull v) {
    float2 r; asm("mov.b64 {%0, %1}, %2;" : "=f"(r.x), "=f"(r.y) : "l"(v));
    return r;
}

// ---------------- device scratch (static, allowed) ----------------
__device__ float g_X0T[(size_t)T_STEPS * BH]; // input proj + layer-0 biases, [t][j][b]
__device__ float g_h0T[BH];                   // layer-0 hidden, [k][b]
__device__ float g_h1T[BH];                   // layer-1 hidden, [k][b]
__device__ float g_ppA[4][BH];                // phase-A CTA-ksplit partials, [sub][j*64+b]
__device__ float g_ppB[4][BH];                // phase-B partials
// tree barrier state: monotonic counters, no resets
__device__ unsigned g_grp[8 * 64];            // 8 group counters, 256B apart
__device__ unsigned g_top;                    // top-level counter
__device__ volatile unsigned g_gen;           // generation (release)

// =================================================================
// Precompute: X0T[t][n][b] = sum_k input[t*64+b, k]*W_ih0[n,k] + b_ih0[n]+b_hh0[n]
// 128x128x16 tile, 8x8 thread tile, f32x2 packed along n.
// =================================================================
__global__ __launch_bounds__(256) void precompute_kernel(
    const float* __restrict__ X,    // [T*B, IN]
    const float* __restrict__ W,    // [H, IN]
    const float* __restrict__ b1,
    const float* __restrict__ b2)
{
    __shared__ float As[16][128];
    __shared__ float Bs[16][128];

    const int tid = threadIdx.x;
    const int n0 = blockIdx.x * 128;
    const int m0 = blockIdx.y * 128;

    const int lr = tid >> 1;
    const int lk = (tid & 1) * 8;
    const int tm = (tid >> 4) * 8;
    const int tn = (tid & 15) * 8;

    ull acc[8][4];
    #pragma unroll
    for (int m = 0; m < 8; m++)
        #pragma unroll
        for (int np = 0; np < 4; np++) acc[m][np] = 0ull;

    for (int k0 = 0; k0 < INDIM; k0 += 16) {
        float4 xa = *(const float4*)&X[(size_t)(m0 + lr) * INDIM + k0 + lk];
        float4 xb = *(const float4*)&X[(size_t)(m0 + lr) * INDIM + k0 + lk + 4];
        float4 wa = *(const float4*)&W[(size_t)(n0 + lr) * INDIM + k0 + lk];
        float4 wb = *(const float4*)&W[(size_t)(n0 + lr) * INDIM + k0 + lk + 4];
        __syncthreads();
        As[lk + 0][lr] = xa.x; As[lk + 1][lr] = xa.y; As[lk + 2][lr] = xa.z; As[lk + 3][lr] = xa.w;
        As[lk + 4][lr] = xb.x; As[lk + 5][lr] = xb.y; As[lk + 6][lr] = xb.z; As[lk + 7][lr] = xb.w;
        Bs[lk + 0][lr] = wa.x; Bs[lk + 1][lr] = wa.y; Bs[lk + 2][lr] = wa.z; Bs[lk + 3][lr] = wa.w;
        Bs[lk + 4][lr] = wb.x; Bs[lk + 5][lr] = wb.y; Bs[lk + 6][lr] = wb.z; Bs[lk + 7][lr] = wb.w;
        __syncthreads();
        #pragma unroll
        for (int kk = 0; kk < 16; kk++) {
            float4 a0 = *(const float4*)&As[kk][tm];
            float4 a1 = *(const float4*)&As[kk][tm + 4];
            ulonglong2 w01 = *(const ulonglong2*)&Bs[kk][tn];
            ulonglong2 w23 = *(const ulonglong2*)&Bs[kk][tn + 4];
            ull wp[4] = {w01.x, w01.y, w23.x, w23.y};
            float am[8] = {a0.x, a0.y, a0.z, a0.w, a1.x, a1.y, a1.z, a1.w};
            #pragma unroll
            for (int m = 0; m < 8; m++) {
                ull ad = pack2(am[m], am[m]);
                #pragma unroll
                for (int np = 0; np < 4; np++)
                    acc[m][np] = fma2(ad, wp[np], acc[m][np]);
            }
        }
    }

    float bs[8];
    #pragma unroll
    for (int j = 0; j < 8; j++) bs[j] = b1[n0 + tn + j] + b2[n0 + tn + j];

    #pragma unroll
    for (int m = 0; m < 8; m++) {
        int row = m0 + tm + m;
        int t = row >> 6, b = row & 63;
        #pragma unroll
        for (int np = 0; np < 4; np++) {
            float2 v = unpack2(acc[m][np]);
            int col = n0 + tn + 2 * np;
            g_X0T[(size_t)t * BH + (size_t)col * 64 + b]       = v.x + bs[2 * np];
            g_X0T[(size_t)t * BH + (size_t)(col + 1) * 64 + b] = v.y + bs[2 * np + 1];
        }
    }
}

// =================================================================
// Persistent recurrent kernel: 128 CTAs x 512 threads.
// =================================================================
// Two-level tree barrier. Counters are monotonic (16 arrivals/group/barrier,
// 8 top arrivals/barrier); the 'gen'-th barrier completes when group counters
// reach 16*(gen+1) and top reaches 8*(gen+1). No resets => short release chain.
__device__ __forceinline__ void grid_barrier(unsigned& gen)
{
    __syncthreads();
    if (threadIdx.x == 0) {
        __threadfence();
        const int grp = blockIdx.x >> 4;            // 8 groups of 16 CTAs
        unsigned a = atomicAdd(&g_grp[grp * 64], 1u);
        if (a == 16u * (gen + 1u) - 1u) {           // last of this group
            unsigned tp = atomicAdd(&g_top, 1u);
            if (tp == 8u * (gen + 1u) - 1u) {       // last group overall
                __threadfence();
                g_gen = gen + 1u;                   // release
            }
        }
        while (g_gen < gen + 1u) { }                // spin (monotonic)
        __threadfence();
    }
    __syncthreads();
    gen++;
}

// Stage one 256k x 64b h panel (64 KB) from global into smem. 512 threads.
__device__ __forceinline__ void stage_panel(float* Hs, const float* __restrict__ src, int tid)
{
    const float4* s = (const float4*)src;
    float4* d = (float4*)Hs;
    #pragma unroll
    for (int i = 0; i < 8; i++) d[i * 512 + tid] = s[i * 512 + tid];
}

// One 256-k panel.  Wp: [256][32] k-major; Hs: [256][64].
// Thread (ksub, bgrp, jgrp) accumulates 2j x 16b (8 b-pairs) over its 32 k.
__device__ __forceinline__ void gemm32(
    const float* __restrict__ Wp, const float* __restrict__ Hs,
    int ksub, int jgrp, int bgrp, ull acc[2][8])
{
    const float* wrow = Wp + (ksub * 32) * 32 + jgrp * 2;
    const float* hrow = Hs + (ksub * 32) * 64 + bgrp * 16;
    #pragma unroll 4
    for (int kk = 0; kk < 32; kk++) {
        float2 w = *(const float2*)(wrow + kk * 32);
        ulonglong2 hA = *(const ulonglong2*)(hrow + kk * 64);
        ulonglong2 hB = *(const ulonglong2*)(hrow + kk * 64 + 4);
        ulonglong2 hC = *(const ulonglong2*)(hrow + kk * 64 + 8);
        ulonglong2 hD = *(const ulonglong2*)(hrow + kk * 64 + 12);
        ull wd0 = pack2(w.x, w.x), wd1 = pack2(w.y, w.y);
        ull hh[8] = {hA.x, hA.y, hB.x, hB.y, hC.x, hC.y, hD.x, hD.y};
        #pragma unroll
        for (int p = 0; p < 8; p++) {
            acc[0][p] = fma2(wd0, hh[p], acc[0][p]);
            acc[1][p] = fma2(wd1, hh[p], acc[1][p]);
        }
    }
}

// Reduce the 8 ksub partials through smem (Red aliases Hs), store partial tile.
// Source thread tid_s = ksub*64 + rem (rem = bgrp*16 + jgrp) wrote
// rw[col*512 + tid_s], col = j*8 + p.  Deterministic order.
__device__ __forceinline__ void reduce_store(
    float* Red, ull acc[2][8], float* __restrict__ gdst, int tid)
{
    __syncthreads();                       // all Hs reads done (Red aliases Hs)
    ull* rw = (ull*)Red;
    #pragma unroll
    for (int j = 0; j < 2; j++)
        #pragma unroll
        for (int p = 0; p < 8; p++)
            rw[(j * 8 + p) * 512 + tid] = acc[j][p];
    __syncthreads();

    #pragma unroll
    for (int q = 0; q < 2; q++) {
        int idx = q * 512 + tid;           // 0..1023
        int col = idx >> 6;                // 0..15  (= j*8 + p)
        int rem = idx & 63;
        ull s = rw[col * 512 + rem];
        #pragma unroll
        for (int ks = 1; ks < 8; ks++)
            s = add2(s, rw[col * 512 + ks * 64 + rem]);
        int jj = col >> 3, p = col & 7;
        int jl = (rem & 15) * 2 + jj;
        int b  = (rem >> 4) * 16 + 2 * p;
        float2 v = unpack2(s);
        *(float2*)&gdst[jl * 64 + b] = v;
    }
}

extern "C" __global__ void __launch_bounds__(NTHR, 1) rnn_persistent(
    const float* __restrict__ h_0,
    const float* __restrict__ W_hh0,
    const float* __restrict__ W_ih1,
    const float* __restrict__ W_hh1,
    const float* __restrict__ b_ih1,
    const float* __restrict__ b_hh1,
    float* __restrict__ out)
{
    extern __shared__ float smem[];
    float* WaS = smem;             // [256][32]  32 KB  (phase-A weight slice)
    float* WbS = smem + 8192;      // [512][32]  64 KB  (phase-B weight slice)
    float* Hs  = smem + 24576;     // [256][64]  64 KB  h panel; aliased as Red

    const int c   = blockIdx.x;
    const int tid = threadIdx.x;

    const int jt  = c >> 2, j0 = jt * 32;
    const int sub = c & 3;
    const int k0A = sub * 256;                 // phase A: K quarter
    const int matB = sub >> 1, khB = sub & 1;  // phase B: matrix / K half
    const int k0B = khB * 512;
    const float* WBsrc = matB ? W_hh1 : W_ih1;

    const int ksub = tid >> 6;                 // 0..7
    const int bgrp = (tid >> 4) & 3;           // 0..3
    const int jgrp = tid & 15;                 // 0..15

    // ---- resident weight slices, transposed to [k][j] ----
    {
        int j  = tid >> 4;                     // 0..31
        int kc = tid & 15;                     // 0..15
        const float* wa = W_hh0 + (size_t)(j0 + j) * HDIM + k0A + kc * 16;
        #pragma unroll 4
        for (int k = 0; k < 16; k++) WaS[(kc * 16 + k) * 32 + j] = wa[k];
        const float* wb = WBsrc + (size_t)(j0 + j) * HDIM + k0B + kc * 32;
        #pragma unroll 4
        for (int k = 0; k < 32; k++) WbS[(kc * 32 + k) * 32 + j] = wb[k];
    }

    // ---- initial state transpose: h_0[layer][b][k] -> g_h{0,1}T[k][b] ----
    {
        int e = c * 512 + tid;
        int j = e >> 6, b = e & 63;
        g_h0T[e] = h_0[(size_t)b * HDIM + j];
        g_h1T[e] = h_0[(size_t)BH + (size_t)b * HDIM + j];
    }

    unsigned gen = 0;
    if (tid == 0) gen = g_gen;
    grid_barrier(gen);

    for (int t = 0; t < T_STEPS; t++) {
        // ===== SLOT 1: combineB(t-1) + gemmA(t) =====
        if (t > 0) {
            int e = c * 512 + tid;
            int j = e >> 6, b = e & 63;
            float v = b_ih1[j] + b_hh1[j]
                    + g_ppB[0][e] + g_ppB[1][e] + g_ppB[2][e] + g_ppB[3][e];
            float rr = tanhf(v);
            g_h1T[e] = rr;
            out[(size_t)(t - 1) * BH + (size_t)b * HDIM + j] = rr;
        }
        {
            ull acc[2][8];
            #pragma unroll
            for (int j = 0; j < 2; j++)
                #pragma unroll
                for (int p = 0; p < 8; p++) acc[j][p] = 0ull;
            stage_panel(Hs, g_h0T + (size_t)k0A * 64, tid);
            __syncthreads();
            gemm32(WaS, Hs, ksub, jgrp, bgrp, acc);
            reduce_store(Hs, acc, g_ppA[sub] + (size_t)j0 * 64, tid);
        }
        grid_barrier(gen);

        // ===== SLOT 2: combineA(t): h0T = tanh(X0T[t] + sum ppA) =====
        {
            int e = c * 512 + tid;
            float v = g_X0T[(size_t)t * BH + e]
                    + g_ppA[0][e] + g_ppA[1][e] + g_ppA[2][e] + g_ppA[3][e];
            g_h0T[e] = tanhf(v);
        }
        grid_barrier(gen);

        // ===== SLOT 3: gemmB(t): ppB[sub] over [W_ih1 | W_hh1] k-range =====
        {
            const float* hb = (matB ? g_h1T : g_h0T) + (size_t)k0B * 64;
            ull acc[2][8];
            #pragma unroll
            for (int j = 0; j < 2; j++)
                #pragma unroll
                for (int p = 0; p < 8; p++) acc[j][p] = 0ull;
            stage_panel(Hs, hb, tid);
            __syncthreads();
            gemm32(WbS, Hs, ksub, jgrp, bgrp, acc);
            __syncthreads();
            stage_panel(Hs, hb + 256 * 64, tid);
            __syncthreads();
            gemm32(WbS + 256 * 32, Hs, ksub, jgrp, bgrp, acc);
            reduce_store(Hs, acc, g_ppB[sub] + (size_t)j0 * 64, tid);
        }
        grid_barrier(gen);
    }

    // ===== final combineB(T-1) + h_n tail =====
    {
        int e = c * 512 + tid;
        int j = e >> 6, b = e & 63;
        float v = b_ih1[j] + b_hh1[j]
                + g_ppB[0][e] + g_ppB[1][e] + g_ppB[2][e] + g_ppB[3][e];
        float rr = tanhf(v);
        out[(size_t)(T_STEPS - 1) * BH + (size_t)b * HDIM + j] = rr;
        out[(size_t)T_STEPS * BH + BH + (size_t)b * HDIM + j]  = rr;       // h1_n
        out[(size_t)T_STEPS * BH + (size_t)b * HDIM + j]       = g_h0T[e]; // h0_n
    }
}

// =================================================================
// Launch
// =================================================================
extern "C" void kernel_launch(void* const* d_in, const int* in_sizes, int n_in,
                              void* d_out, int out_size)
{
    const float* input = (const float*)d_in[0];
    const float* h_0   = (const float*)d_in[1];
    const float* W_ih0 = (const float*)d_in[2];
    const float* b_ih0 = (const float*)d_in[3];
    const float* W_hh0 = (const float*)d_in[4];
    const float* b_hh0 = (const float*)d_in[5];
    const float* W_ih1 = (const float*)d_in[6];
    const float* b_ih1 = (const float*)d_in[7];
    const float* W_hh1 = (const float*)d_in[8];
    const float* b_hh1 = (const float*)d_in[9];
    float* out = (float*)d_out;

    (void)in_sizes; (void)n_in; (void)out_size;

    const int SMEM_BYTES = (8192 + 16384 + 16384) * 4;   // 163840
    cudaFuncSetAttribute(rnn_persistent,
                         cudaFuncAttributeMaxDynamicSharedMemorySize,
                         SMEM_BYTES);

    // 1) X0T = input @ W_ih0^T + b_ih0 + b_hh0
    {
        dim3 grid(HDIM / 128, (T_STEPS * BATCH) / 128);
        precompute_kernel<<<grid, 256>>>(input, W_ih0, b_ih0, b_hh0);
    }

    // 2) persistent recurrence (single kernel, 3 tree-barriers/step)
    rnn_persistent<<<NCTA, NTHR, SMEM_BYTES>>>(h_0, W_hh0, W_ih1, W_hh1,
                                               b_ih1, b_hh1, out);
}

// round 14
// speedup vs baseline: 1.0855x; 1.0855x over previous
#include <cuda_runtime.h>
#include <math.h>

#define T_STEPS 512
#define BATCH   64
#define INDIM   1024
#define HDIM    1024
#define BH      (BATCH * HDIM)      // 65536
#define NCTA    128
#define NTHR    256

typedef unsigned long long ull;

// ---------------- packed f32x2 helpers ----------------
__device__ __forceinline__ ull fma2(ull a, ull b, ull c) {
    ull d; asm("fma.rn.f32x2 %0, %1, %2, %3;" : "=l"(d) : "l"(a), "l"(b), "l"(c));
    return d;
}
__device__ __forceinline__ ull add2(ull a, ull b) {
    ull d; asm("add.rn.f32x2 %0, %1, %2;" : "=l"(d) : "l"(a), "l"(b));
    return d;
}
__device__ __forceinline__ ull pack2(float x, float y) {
    ull d; asm("mov.b64 %0, {%1, %2};" : "=l"(d) : "f"(x), "f"(y));
    return d;
}
__device__ __forceinline__ float2 unpack2(ull v) {
    float2 r; asm("mov.b64 {%0, %1}, %2;" : "=f"(r.x), "=f"(r.y) : "l"(v));
    return r;
}

// ---------------- device scratch (static, allowed) ----------------
__device__ float g_X0T[(size_t)T_STEPS * BH]; // input proj + layer-0 biases, [t][j][b]
__device__ float g_h0T[2][BH];                // layer-0 hidden, ping-pong, [k][b]
__device__ float g_h1T[2][BH];                // layer-1 hidden, ping-pong, [k][b]
__device__ float g_ppA[4][BH];                // phase-A CTA-ksplit partials, [sub][j*64+b]
__device__ float g_ppB[4][BH];                // phase-B partials
// tree barrier state: monotonic counters, no resets
__device__ unsigned g_grp[8 * 64];            // 8 group counters, 256B apart
__device__ unsigned g_top;                    // top-level counter
__device__ volatile unsigned g_gen;           // generation (release)
// per-j-tile mini-barrier counters (32 groups of 4 CTAs), monotonic
__device__ unsigned g_mA[32 * 64];
__device__ unsigned g_mB[32 * 64];

// =================================================================
// Precompute: X0T[t][n][b] = sum_k input[t*64+b, k]*W_ih0[n,k] + b_ih0[n]+b_hh0[n]
// 128x128x16 tile, 8x8 thread tile, f32x2 packed along n.
// =================================================================
__global__ __launch_bounds__(256) void precompute_kernel(
    const float* __restrict__ X,    // [T*B, IN]
    const float* __restrict__ W,    // [H, IN]
    const float* __restrict__ b1,
    const float* __restrict__ b2)
{
    __shared__ float As[16][128];
    __shared__ float Bs[16][128];

    const int tid = threadIdx.x;
    const int n0 = blockIdx.x * 128;
    const int m0 = blockIdx.y * 128;

    const int lr = tid >> 1;
    const int lk = (tid & 1) * 8;
    const int tm = (tid >> 4) * 8;
    const int tn = (tid & 15) * 8;

    ull acc[8][4];
    #pragma unroll
    for (int m = 0; m < 8; m++)
        #pragma unroll
        for (int np = 0; np < 4; np++) acc[m][np] = 0ull;

    for (int k0 = 0; k0 < INDIM; k0 += 16) {
        float4 xa = *(const float4*)&X[(size_t)(m0 + lr) * INDIM + k0 + lk];
        float4 xb = *(const float4*)&X[(size_t)(m0 + lr) * INDIM + k0 + lk + 4];
        float4 wa = *(const float4*)&W[(size_t)(n0 + lr) * INDIM + k0 + lk];
        float4 wb = *(const float4*)&W[(size_t)(n0 + lr) * INDIM + k0 + lk + 4];
        __syncthreads();
        As[lk + 0][lr] = xa.x; As[lk + 1][lr] = xa.y; As[lk + 2][lr] = xa.z; As[lk + 3][lr] = xa.w;
        As[lk + 4][lr] = xb.x; As[lk + 5][lr] = xb.y; As[lk + 6][lr] = xb.z; As[lk + 7][lr] = xb.w;
        Bs[lk + 0][lr] = wa.x; Bs[lk + 1][lr] = wa.y; Bs[lk + 2][lr] = wa.z; Bs[lk + 3][lr] = wa.w;
        Bs[lk + 4][lr] = wb.x; Bs[lk + 5][lr] = wb.y; Bs[lk + 6][lr] = wb.z; Bs[lk + 7][lr] = wb.w;
        __syncthreads();
        #pragma unroll
        for (int kk = 0; kk < 16; kk++) {
            float4 a0 = *(const float4*)&As[kk][tm];
            float4 a1 = *(const float4*)&As[kk][tm + 4];
            ulonglong2 w01 = *(const ulonglong2*)&Bs[kk][tn];
            ulonglong2 w23 = *(const ulonglong2*)&Bs[kk][tn + 4];
            ull wp[4] = {w01.x, w01.y, w23.x, w23.y};
            float am[8] = {a0.x, a0.y, a0.z, a0.w, a1.x, a1.y, a1.z, a1.w};
            #pragma unroll
            for (int m = 0; m < 8; m++) {
                ull ad = pack2(am[m], am[m]);
                #pragma unroll
                for (int np = 0; np < 4; np++)
                    acc[m][np] = fma2(ad, wp[np], acc[m][np]);
            }
        }
    }

    float bs[8];
    #pragma unroll
    for (int j = 0; j < 8; j++) bs[j] = b1[n0 + tn + j] + b2[n0 + tn + j];

    #pragma unroll
    for (int m = 0; m < 8; m++) {
        int row = m0 + tm + m;
        int t = row >> 6, b = row & 63;
        #pragma unroll
        for (int np = 0; np < 4; np++) {
            float2 v = unpack2(acc[m][np]);
            int col = n0 + tn + 2 * np;
            g_X0T[(size_t)t * BH + (size_t)col * 64 + b]       = v.x + bs[2 * np];
            g_X0T[(size_t)t * BH + (size_t)(col + 1) * 64 + b] = v.y + bs[2 * np + 1];
        }
    }
}

// =================================================================
// Persistent recurrent kernel: 128 CTAs x 256 threads, 2 grid barriers/step.
// =================================================================
// Two-level tree barrier (monotonic counters; R13 logic).
__device__ __forceinline__ void grid_barrier(unsigned& gen)
{
    __syncthreads();
    if (threadIdx.x == 0) {
        __threadfence();
        const int grp = blockIdx.x >> 4;            // 8 groups of 16 CTAs
        unsigned a = atomicAdd(&g_grp[grp * 64], 1u);
        if (a == 16u * (gen + 1u) - 1u) {
            unsigned tp = atomicAdd(&g_top, 1u);
            if (tp == 8u * (gen + 1u) - 1u) {
                __threadfence();
                g_gen = gen + 1u;
            }
        }
        while (g_gen < gen + 1u) { }
        __threadfence();
    }
    __syncthreads();
    gen++;
}

// 4-CTA mini-barrier on a monotonic counter (one per j-tile group).
__device__ __forceinline__ void minibar(unsigned* ctr, unsigned target)
{
    __syncthreads();
    if (threadIdx.x == 0) {
        __threadfence();
        atomicAdd(ctr, 1u);
        while (*(volatile unsigned*)ctr < target) { }
        __threadfence();
    }
    __syncthreads();
}

// Stage one 256k x 64b h panel (64 KB) from global into smem. 256 threads.
__device__ __forceinline__ void stage_panel(float* Hs, const float* __restrict__ src, int tid)
{
    const float4* s = (const float4*)src;
    float4* d = (float4*)Hs;
    #pragma unroll
    for (int i = 0; i < 16; i++) d[i * 256 + tid] = s[i * 256 + tid];
}

// One 256-k panel.  Wp: [256][32] k-major; Hs: [256][64].
// Thread (ksub,bgrp,jgrp) accumulates 4j x 16b (8 b-pairs) over its 32 k.
__device__ __forceinline__ void gemm32(
    const float* __restrict__ Wp, const float* __restrict__ Hs,
    int ksub, int jgrp, int bgrp, ull acc[4][8])
{
    const float* wrow = Wp + (ksub * 32) * 32 + jgrp * 4;
    const float* hrow = Hs + (ksub * 32) * 64 + bgrp * 16;
    #pragma unroll 4
    for (int kk = 0; kk < 32; kk++) {
        float4 w = *(const float4*)(wrow + kk * 32);
        ulonglong2 hA = *(const ulonglong2*)(hrow + kk * 64);
        ulonglong2 hB = *(const ulonglong2*)(hrow + kk * 64 + 4);
        ulonglong2 hC = *(const ulonglong2*)(hrow + kk * 64 + 8);
        ulonglong2 hD = *(const ulonglong2*)(hrow + kk * 64 + 12);
        ull wd0 = pack2(w.x, w.x), wd1 = pack2(w.y, w.y);
        ull wd2 = pack2(w.z, w.z), wd3 = pack2(w.w, w.w);
        ull hh[8] = {hA.x, hA.y, hB.x, hB.y, hC.x, hC.y, hD.x, hD.y};
        #pragma unroll
        for (int p = 0; p < 8; p++) {
            acc[0][p] = fma2(wd0, hh[p], acc[0][p]);
            acc[1][p] = fma2(wd1, hh[p], acc[1][p]);
            acc[2][p] = fma2(wd2, hh[p], acc[2][p]);
            acc[3][p] = fma2(wd3, hh[p], acc[3][p]);
        }
    }
}

// Reduce the 8 ksub partials through smem (Red aliases Hs), store partial tile.
__device__ __forceinline__ void reduce_store(
    float* Red, ull acc[4][8], float* __restrict__ gdst, int tid)
{
    __syncthreads();                       // all Hs reads done (Red aliases Hs)
    ull* rw = (ull*)Red;
    #pragma unroll
    for (int j = 0; j < 4; j++)
        #pragma unroll
        for (int p = 0; p < 8; p++)
            rw[(j * 8 + p) * 256 + tid] = acc[j][p];
    __syncthreads();

    const int rowidx = tid & 31;
    const int grp    = tid >> 5;
    const int jgrp_o = rowidx & 7;
    const int bgrp_o = rowidx >> 3;
    #pragma unroll
    for (int q = 0; q < 4; q++) {
        int col = grp * 4 + q;             // = j*8 + p
        ull s = rw[col * 256 + rowidx];
        #pragma unroll
        for (int ks = 1; ks < 8; ks++)
            s = add2(s, rw[col * 256 + ks * 32 + rowidx]);
        int jj = col >> 3, p = col & 7;
        int jl = jgrp_o * 4 + jj;
        int b  = bgrp_o * 16 + 2 * p;
        float2 v = unpack2(s);
        *(float2*)&gdst[jl * 64 + b] = v;
    }
}

extern "C" __global__ void __launch_bounds__(NTHR, 1) rnn_persistent(
    const float* __restrict__ h_0,
    const float* __restrict__ W_hh0,
    const float* __restrict__ W_ih1,
    const float* __restrict__ W_hh1,
    const float* __restrict__ b_ih1,
    const float* __restrict__ b_hh1,
    float* __restrict__ out)
{
    extern __shared__ float smem[];
    float* WaS = smem;             // [256][32]  32 KB  (phase-A weight slice)
    float* WbS = smem + 8192;      // [512][32]  64 KB  (phase-B weight slice)
    float* Hs  = smem + 24576;     // [256][64]  64 KB  h panel; aliased as Red

    const int c   = blockIdx.x;
    const int tid = threadIdx.x;

    const int jt  = c >> 2, j0 = jt * 32;
    const int sub = c & 3;
    const int k0A = sub * 256;                 // phase A: K quarter
    const int matB = sub >> 1, khB = sub & 1;  // phase B: matrix / K half
    const int k0B = khB * 512;
    const float* WBsrc = matB ? W_hh1 : W_ih1;

    const int ksub = tid >> 5;                 // 0..7
    const int bgrp = (tid >> 3) & 3;           // 0..3
    const int jgrp = tid & 7;                  // 0..7

    // per-thread combine indices (2 elements: r=0,1)
    const int e0 = c * 512 + tid;
    const int e1 = e0 + 256;
    const int jA0 = e0 >> 6, bA0 = e0 & 63;
    const int jA1 = e1 >> 6, bA1 = e1 & 63;

    // ---- resident weight slices, transposed to [k][j] ----
    {
        int j  = tid >> 3;
        int kc = tid & 7;
        const float* wa = W_hh0 + (size_t)(j0 + j) * HDIM + k0A + kc * 32;
        #pragma unroll 8
        for (int k = 0; k < 32; k++) WaS[(kc * 32 + k) * 32 + j] = wa[k];
        const float* wb = WBsrc + (size_t)(j0 + j) * HDIM + k0B + kc * 64;
        #pragma unroll 8
        for (int k = 0; k < 64; k++) WbS[(kc * 64 + k) * 32 + j] = wb[k];
    }

    // ---- initial state transpose: h_0[layer][b][k] -> buffers[0] ----
    #pragma unroll
    for (int r = 0; r < 2; r++) {
        int e = r ? e1 : e0;
        int j = e >> 6, b = e & 63;
        g_h0T[0][e] = h_0[(size_t)b * HDIM + j];
        g_h1T[0][e] = h_0[(size_t)BH + (size_t)b * HDIM + j];
    }

    // t-invariant layer-1 bias for this thread's combine slice
    const float biasB0 = b_ih1[jA0] + b_hh1[jA0];
    const float biasB1 = b_ih1[jA1] + b_hh1[jA1];

    unsigned gen = 0, mbA = 0, mbB = 0;
    if (tid == 0) {
        gen = g_gen;
        mbA = g_mA[jt * 64];
        mbB = g_mB[jt * 64];
    }
    grid_barrier(gen);   // weights + initial states visible everywhere

    for (int t = 0; t < T_STEPS; t++) {
        const int rp = t & 1, wp = (t + 1) & 1;   // read / write parity

        // =================== PHASE 1: gemmA + combineA ===================
        // prefetch X0T slice (consumed after mini-barrier)
        float xv0 = g_X0T[(size_t)t * BH + e0];
        float xv1 = g_X0T[(size_t)t * BH + e1];
        {
            ull acc[4][8];
            #pragma unroll
            for (int j = 0; j < 4; j++)
                #pragma unroll
                for (int p = 0; p < 8; p++) acc[j][p] = 0ull;
            stage_panel(Hs, g_h0T[rp] + (size_t)k0A * 64, tid);
            __syncthreads();
            gemm32(WaS, Hs, ksub, jgrp, bgrp, acc);
            reduce_store(Hs, acc, g_ppA[sub] + (size_t)j0 * 64, tid);
        }
        if (tid == 0) mbA++;                     // track target on tid0
        minibar(&g_mA[jt * 64], mbA);            // 4 group CTAs' partials ready
        {
            float v0 = xv0 + g_ppA[0][e0] + g_ppA[1][e0] + g_ppA[2][e0] + g_ppA[3][e0];
            float v1 = xv1 + g_ppA[0][e1] + g_ppA[1][e1] + g_ppA[2][e1] + g_ppA[3][e1];
            float r0 = tanhf(v0), r1 = tanhf(v1);
            g_h0T[wp][e0] = r0;
            g_h0T[wp][e1] = r1;
            if (t == T_STEPS - 1) {
                out[(size_t)T_STEPS * BH + (size_t)bA0 * HDIM + jA0] = r0;
                out[(size_t)T_STEPS * BH + (size_t)bA1 * HDIM + jA1] = r1;
            }
        }
        grid_barrier(gen);   // all h0T(t) columns visible

        // =================== PHASE 2: gemmB + combineB ===================
        {
            const float* hb = (matB ? g_h1T[rp] : g_h0T[wp]) + (size_t)k0B * 64;
            ull acc[4][8];
            #pragma unroll
            for (int j = 0; j < 4; j++)
                #pragma unroll
                for (int p = 0; p < 8; p++) acc[j][p] = 0ull;
            stage_panel(Hs, hb, tid);
            __syncthreads();
            gemm32(WbS, Hs, ksub, jgrp, bgrp, acc);
            __syncthreads();
            stage_panel(Hs, hb + 256 * 64, tid);
            __syncthreads();
            gemm32(WbS + 256 * 32, Hs, ksub, jgrp, bgrp, acc);
            reduce_store(Hs, acc, g_ppB[sub] + (size_t)j0 * 64, tid);
        }
        if (tid == 0) mbB++;
        minibar(&g_mB[jt * 64], mbB);
        {
            float v0 = biasB0 + g_ppB[0][e0] + g_ppB[1][e0] + g_ppB[2][e0] + g_ppB[3][e0];
            float v1 = biasB1 + g_ppB[0][e1] + g_ppB[1][e1] + g_ppB[2][e1] + g_ppB[3][e1];
            float r0 = tanhf(v0), r1 = tanhf(v1);
            g_h1T[wp][e0] = r0;
            g_h1T[wp][e1] = r1;
            out[(size_t)t * BH + (size_t)bA0 * HDIM + jA0] = r0;
            out[(size_t)t * BH + (size_t)bA1 * HDIM + jA1] = r1;
            if (t == T_STEPS - 1) {
                out[(size_t)T_STEPS * BH + BH + (size_t)bA0 * HDIM + jA0] = r0;
                out[(size_t)T_STEPS * BH + BH + (size_t)bA1 * HDIM + jA1] = r1;
            }
        }
        grid_barrier(gen);   // all h1T(t) columns visible
    }
}

// =================================================================
// Launch
// =================================================================
extern "C" void kernel_launch(void* const* d_in, const int* in_sizes, int n_in,
                              void* d_out, int out_size)
{
    const float* input = (const float*)d_in[0];
    const float* h_0   = (const float*)d_in[1];
    const float* W_ih0 = (const float*)d_in[2];
    const float* b_ih0 = (const float*)d_in[3];
    const float* W_hh0 = (const float*)d_in[4];
    const float* b_hh0 = (const float*)d_in[5];
    const float* W_ih1 = (const float*)d_in[6];
    const float* b_ih1 = (const float*)d_in[7];
    const float* W_hh1 = (const float*)d_in[8];
    const float* b_hh1 = (const float*)d_in[9];
    float* out = (float*)d_out;

    (void)in_sizes; (void)n_in; (void)out_size;

    const int SMEM_BYTES = (8192 + 16384 + 16384) * 4;   // 163840
    cudaFuncSetAttribute(rnn_persistent,
                         cudaFuncAttributeMaxDynamicSharedMemorySize,
                         SMEM_BYTES);

    // 1) X0T = input @ W_ih0^T + b_ih0 + b_hh0
    {
        dim3 grid(HDIM / 128, (T_STEPS * BATCH) / 128);
        precompute_kernel<<<grid, 256>>>(input, W_ih0, b_ih0, b_hh0);
    }

    // 2) persistent recurrence (single kernel, 2 grid barriers/step)
    rnn_persistent<<<NCTA, NTHR, SMEM_BYTES>>>(h_0, W_hh0, W_ih1, W_hh1,
                                               b_ih1, b_hh1, out);
}

// round 17
// speedup vs baseline: 1.2341x; 1.1369x over previous
#include <cuda_runtime.h>
#include <math.h>

#define T_STEPS 512
#define BATCH   64
#define INDIM   1024
#define HDIM    1024
#define BH      (BATCH * HDIM)      // 65536
#define NCTA    128
#define NTHR    256

typedef unsigned long long ull;

// ---------------- packed f32x2 helpers ----------------
__device__ __forceinline__ ull fma2(ull a, ull b, ull c) {
    ull d; asm("fma.rn.f32x2 %0, %1, %2, %3;" : "=l"(d) : "l"(a), "l"(b), "l"(c));
    return d;
}
__device__ __forceinline__ ull add2(ull a, ull b) {
    ull d; asm("add.rn.f32x2 %0, %1, %2;" : "=l"(d) : "l"(a), "l"(b));
    return d;
}
__device__ __forceinline__ ull pack2(float x, float y) {
    ull d; asm("mov.b64 %0, {%1, %2};" : "=l"(d) : "f"(x), "f"(y));
    return d;
}
__device__ __forceinline__ float2 unpack2(ull v) {
    float2 r; asm("mov.b64 {%0, %1}, %2;" : "=f"(r.x), "=f"(r.y) : "l"(v));
    return r;
}

// ---------------- device scratch (static, allowed) ----------------
__device__ float g_X0T[(size_t)T_STEPS * BH]; // input proj + layer-0 biases, [t][j][b]
__device__ float g_h0T[2][BH];                // layer-0 hidden, ping-pong, [k][b]
__device__ float g_h1T[2][BH];                // layer-1 hidden, ping-pong, [k][b]
__device__ float g_ppA[4][BH];                // phase-A ksplit partials, [sub][j*64+b]
__device__ float g_ppB[4][BH];                // phase-B partials
// init-barrier state (reset each launch)
__device__ unsigned g_grp[8 * 64];
__device__ unsigned g_top;
__device__ volatile unsigned g_gen;
// per-j-group sync state (reset each launch); 64B spacing
__device__ unsigned g_mA[32 * 16];            // minibar: gemmA arrivals
__device__ unsigned g_mB[32 * 16];            // minibar: gemmB arrivals
__device__ unsigned g_fh0[32 * 16];           // combineA published (h0(t) group done)
__device__ unsigned g_fh1[32 * 16];           // combineB published (h1(t) group done)

// =================================================================
// Reset sync counters (runs before the persistent kernel each launch)
// =================================================================
__global__ void reset_kernel()
{
    int i = threadIdx.x;
    if (i < 512) { if (i < 32 * 16) { g_mA[i] = 0; g_mB[i] = 0; g_fh0[i] = 0; g_fh1[i] = 0; } }
    if (i < 8 * 64) g_grp[i] = 0;
    if (i == 0) { g_top = 0; *(unsigned*)&g_gen = 0; }
}

// =================================================================
// Precompute: X0T[t][n][b] = sum_k input[t*64+b, k]*W_ih0[n,k] + b_ih0[n]+b_hh0[n]
// 128x128x16 tile, 8x8 thread tile, f32x2 packed along n.
// =================================================================
__global__ __launch_bounds__(256) void precompute_kernel(
    const float* __restrict__ X,    // [T*B, IN]
    const float* __restrict__ W,    // [H, IN]
    const float* __restrict__ b1,
    const float* __restrict__ b2)
{
    __shared__ float As[16][128];
    __shared__ float Bs[16][128];

    const int tid = threadIdx.x;
    const int n0 = blockIdx.x * 128;
    const int m0 = blockIdx.y * 128;

    const int lr = tid >> 1;
    const int lk = (tid & 1) * 8;
    const int tm = (tid >> 4) * 8;
    const int tn = (tid & 15) * 8;

    ull acc[8][4];
    #pragma unroll
    for (int m = 0; m < 8; m++)
        #pragma unroll
        for (int np = 0; np < 4; np++) acc[m][np] = 0ull;

    for (int k0 = 0; k0 < INDIM; k0 += 16) {
        float4 xa = *(const float4*)&X[(size_t)(m0 + lr) * INDIM + k0 + lk];
        float4 xb = *(const float4*)&X[(size_t)(m0 + lr) * INDIM + k0 + lk + 4];
        float4 wa = *(const float4*)&W[(size_t)(n0 + lr) * INDIM + k0 + lk];
        float4 wb = *(const float4*)&W[(size_t)(n0 + lr) * INDIM + k0 + lk + 4];
        __syncthreads();
        As[lk + 0][lr] = xa.x; As[lk + 1][lr] = xa.y; As[lk + 2][lr] = xa.z; As[lk + 3][lr] = xa.w;
        As[lk + 4][lr] = xb.x; As[lk + 5][lr] = xb.y; As[lk + 6][lr] = xb.z; As[lk + 7][lr] = xb.w;
        Bs[lk + 0][lr] = wa.x; Bs[lk + 1][lr] = wa.y; Bs[lk + 2][lr] = wa.z; Bs[lk + 3][lr] = wa.w;
        Bs[lk + 4][lr] = wb.x; Bs[lk + 5][lr] = wb.y; Bs[lk + 6][lr] = wb.z; Bs[lk + 7][lr] = wb.w;
        __syncthreads();
        #pragma unroll
        for (int kk = 0; kk < 16; kk++) {
            float4 a0 = *(const float4*)&As[kk][tm];
            float4 a1 = *(const float4*)&As[kk][tm + 4];
            ulonglong2 w01 = *(const ulonglong2*)&Bs[kk][tn];
            ulonglong2 w23 = *(const ulonglong2*)&Bs[kk][tn + 4];
            ull wp[4] = {w01.x, w01.y, w23.x, w23.y};
            float am[8] = {a0.x, a0.y, a0.z, a0.w, a1.x, a1.y, a1.z, a1.w};
            #pragma unroll
            for (int m = 0; m < 8; m++) {
                ull ad = pack2(am[m], am[m]);
                #pragma unroll
                for (int np = 0; np < 4; np++)
                    acc[m][np] = fma2(ad, wp[np], acc[m][np]);
            }
        }
    }

    float bs[8];
    #pragma unroll
    for (int j = 0; j < 8; j++) bs[j] = b1[n0 + tn + j] + b2[n0 + tn + j];

    #pragma unroll
    for (int m = 0; m < 8; m++) {
        int row = m0 + tm + m;
        int t = row >> 6, b = row & 63;
        #pragma unroll
        for (int np = 0; np < 4; np++) {
            float2 v = unpack2(acc[m][np]);
            int col = n0 + tn + 2 * np;
            g_X0T[(size_t)t * BH + (size_t)col * 64 + b]       = v.x + bs[2 * np];
            g_X0T[(size_t)t * BH + (size_t)(col + 1) * 64 + b] = v.y + bs[2 * np + 1];
        }
    }
}

// =================================================================
// Persistent recurrent kernel: dataflow sync (no grid barriers in loop)
// =================================================================
// One-time init barrier (tree, counters reset each launch).
__device__ __forceinline__ void init_barrier()
{
    __threadfence();
    __syncthreads();
    if (threadIdx.x == 0) {
        const int grp = blockIdx.x >> 4;
        unsigned a = atomicAdd(&g_grp[grp * 64], 1u);
        if (a == 15u) {
            unsigned tp = atomicAdd(&g_top, 1u);
            if (tp == 7u) { __threadfence(); g_gen = 1u; }
        }
        while (g_gen < 1u) { }
        __threadfence();
    }
    __syncthreads();
}

// 4-CTA minibar on a monotonic counter; absolute target.
__device__ __forceinline__ void minibar(unsigned* ctr, unsigned target)
{
    __threadfence();
    __syncthreads();
    if (threadIdx.x == 0) {
        atomicAdd(ctr, 1u);
        while (*(volatile unsigned*)ctr < target) { }
        __threadfence();
    }
    __syncthreads();
}

// Publish group progress: all combine stores visible, then +1.
__device__ __forceinline__ void publish(unsigned* ctr)
{
    __threadfence();
    __syncthreads();
    if (threadIdx.x == 0) atomicAdd(ctr, 1u);
}

// Wait: threads 0..n-1 poll one counter each until >= its threshold.
__device__ __forceinline__ void wait_ctr(const volatile unsigned* p, unsigned thr)
{
    while (*p < thr) { }
}

// Stage one 256k x 64b h panel (64 KB) global->smem via L2 (.cg).
__device__ __forceinline__ void stage_panel(float* Hs, const float* __restrict__ src, int tid)
{
    const float4* s = (const float4*)src;
    float4* d = (float4*)Hs;
    #pragma unroll
    for (int i = 0; i < 16; i++) d[i * 256 + tid] = __ldcg(s + i * 256 + tid);
}

// One 256-k panel.  Wp: [256][32] k-major; Hs: [256][64].
// Thread (ksub,bgrp,jgrp) accumulates 4j x 16b (8 b-pairs) over its 32 k.
__device__ __forceinline__ void gemm32(
    const float* __restrict__ Wp, const float* __restrict__ Hs,
    int ksub, int jgrp, int bgrp, ull acc[4][8])
{
    const float* wrow = Wp + (ksub * 32) * 32 + jgrp * 4;
    const float* hrow = Hs + (ksub * 32) * 64 + bgrp * 16;
    #pragma unroll 4
    for (int kk = 0; kk < 32; kk++) {
        float4 w = *(const float4*)(wrow + kk * 32);
        ulonglong2 hA = *(const ulonglong2*)(hrow + kk * 64);
        ulonglong2 hB = *(const ulonglong2*)(hrow + kk * 64 + 4);
        ulonglong2 hC = *(const ulonglong2*)(hrow + kk * 64 + 8);
        ulonglong2 hD = *(const ulonglong2*)(hrow + kk * 64 + 12);
        ull wd0 = pack2(w.x, w.x), wd1 = pack2(w.y, w.y);
        ull wd2 = pack2(w.z, w.z), wd3 = pack2(w.w, w.w);
        ull hh[8] = {hA.x, hA.y, hB.x, hB.y, hC.x, hC.y, hD.x, hD.y};
        #pragma unroll
        for (int p = 0; p < 8; p++) {
            acc[0][p] = fma2(wd0, hh[p], acc[0][p]);
            acc[1][p] = fma2(wd1, hh[p], acc[1][p]);
            acc[2][p] = fma2(wd2, hh[p], acc[2][p]);
            acc[3][p] = fma2(wd3, hh[p], acc[3][p]);
        }
    }
}

// Reduce the 8 ksub partials through smem (Red aliases Hs), store partial tile.
__device__ __forceinline__ void reduce_store(
    float* Red, ull acc[4][8], float* __restrict__ gdst, int tid)
{
    __syncthreads();                       // all Hs reads done (Red aliases Hs)
    ull* rw = (ull*)Red;
    #pragma unroll
    for (int j = 0; j < 4; j++)
        #pragma unroll
        for (int p = 0; p < 8; p++)
            rw[(j * 8 + p) * 256 + tid] = acc[j][p];
    __syncthreads();

    const int rowidx = tid & 31;
    const int grp    = tid >> 5;
    const int jgrp_o = rowidx & 7;
    const int bgrp_o = rowidx >> 3;
    #pragma unroll
    for (int q = 0; q < 4; q++) {
        int col = grp * 4 + q;             // = j*8 + p
        ull s = rw[col * 256 + rowidx];
        #pragma unroll
        for (int ks = 1; ks < 8; ks++)
            s = add2(s, rw[col * 256 + ks * 32 + rowidx]);
        int jj = col >> 3, p = col & 7;
        int jl = jgrp_o * 4 + jj;
        int b  = bgrp_o * 16 + 2 * p;
        float2 v = unpack2(s);
        *(float2*)&gdst[jl * 64 + b] = v;
    }
}

extern "C" __global__ void __launch_bounds__(NTHR, 1) rnn_persistent(
    const float* __restrict__ h_0,
    const float* __restrict__ W_hh0,
    const float* __restrict__ W_ih1,
    const float* __restrict__ W_hh1,
    const float* __restrict__ b_ih1,
    const float* __restrict__ b_hh1,
    float* __restrict__ out)
{
    extern __shared__ float smem[];
    float* WaS = smem;             // [256][32]  32 KB  (phase-A weight slice)
    float* WbS = smem + 8192;      // [512][32]  64 KB  (phase-B weight slice)
    float* Hs  = smem + 24576;     // [256][64]  64 KB  h panel; aliased as Red

    const int c   = blockIdx.x;
    const int tid = threadIdx.x;

    const int jt  = c >> 2, j0 = jt * 32;
    const int sub = c & 3;
    const int k0A = sub * 256;                 // phase A: K quarter
    const int matB = sub >> 1, khB = sub & 1;  // phase B: matrix / K half
    const int k0B = khB * 512;
    const float* WBsrc = matB ? W_hh1 : W_ih1;

    const int ksub = tid >> 5;
    const int bgrp = (tid >> 3) & 3;
    const int jgrp = tid & 7;

    // combine slice (CTA c owns j-cols [c*8, c*8+8) -- inside its own group)
    const int e0 = c * 512 + tid;
    const int e1 = e0 + 256;
    const int jA0 = e0 >> 6, bA0 = e0 & 63;
    const int jA1 = e1 >> 6, bA1 = e1 & 63;

    // wait-list assignments (per thread)
    // gemmA: threads 0..8 poll fh0[sub*8 + tid] (tid<8) or fh0[jt] (tid==8)
    const int gA = (tid < 8) ? (sub * 8 + tid) : jt;
    // gemmB: threads 0..16: mat0 -> fh0[khB*16+tid] (tid<16), fh1[jt] (tid==16)
    //                        mat1 -> fh1[khB*16+tid] (tid<16), fh1[jt] (tid==16)
    const int gB = (tid < 16) ? (khB * 16 + tid) : jt;

    // ---- resident weight slices, transposed to [k][j] ----
    {
        int j  = tid >> 3;
        int kc = tid & 7;
        const float* wa = W_hh0 + (size_t)(j0 + j) * HDIM + k0A + kc * 32;
        #pragma unroll 8
        for (int k = 0; k < 32; k++) WaS[(kc * 32 + k) * 32 + j] = wa[k];
        const float* wb = WBsrc + (size_t)(j0 + j) * HDIM + k0B + kc * 64;
        #pragma unroll 8
        for (int k = 0; k < 64; k++) WbS[(kc * 64 + k) * 32 + j] = wb[k];
    }

    // ---- initial state transpose: h_0[layer][b][k] -> buffers[0] ----
    #pragma unroll
    for (int r = 0; r < 2; r++) {
        int e = r ? e1 : e0;
        int j = e >> 6, b = e & 63;
        g_h0T[0][e] = h_0[(size_t)b * HDIM + j];
        g_h1T[0][e] = h_0[(size_t)BH + (size_t)b * HDIM + j];
    }

    const float biasB0 = b_ih1[jA0] + b_hh1[jA0];
    const float biasB1 = b_ih1[jA1] + b_hh1[jA1];

    init_barrier();   // weights + initial states visible; counters are zeroed

    for (int t = 0; t < T_STEPS; t++) {
        const int rp = t & 1, wp = (t + 1) & 1;

        // =================== PHASE A ===================
        // wait: h0(t-1) producers (8 quarter groups) + own group (ppA WAR)
        if (t > 0) {
            if (tid < 9) wait_ctr(&g_fh0[gA * 16], 4u * t);
            __syncthreads();
        }
        float xv0 = __ldcs(&g_X0T[(size_t)t * BH + e0]);
        float xv1 = __ldcs(&g_X0T[(size_t)t * BH + e1]);
        {
            ull acc[4][8];
            #pragma unroll
            for (int j = 0; j < 4; j++)
                #pragma unroll
                for (int p = 0; p < 8; p++) acc[j][p] = 0ull;
            stage_panel(Hs, g_h0T[rp] + (size_t)k0A * 64, tid);
            __syncthreads();
            gemm32(WaS, Hs, ksub, jgrp, bgrp, acc);
            reduce_store(Hs, acc, g_ppA[sub] + (size_t)j0 * 64, tid);
        }
        minibar(&g_mA[jt * 16], 4u * (t + 1));
        {
            float v0 = xv0 + __ldcg(&g_ppA[0][e0]) + __ldcg(&g_ppA[1][e0])
                           + __ldcg(&g_ppA[2][e0]) + __ldcg(&g_ppA[3][e0]);
            float v1 = xv1 + __ldcg(&g_ppA[0][e1]) + __ldcg(&g_ppA[1][e1])
                           + __ldcg(&g_ppA[2][e1]) + __ldcg(&g_ppA[3][e1]);
            float r0 = tanhf(v0), r1 = tanhf(v1);
            g_h0T[wp][e0] = r0;
            g_h0T[wp][e1] = r1;
            if (t == T_STEPS - 1) {
                out[(size_t)T_STEPS * BH + (size_t)bA0 * HDIM + jA0] = r0;
                out[(size_t)T_STEPS * BH + (size_t)bA1 * HDIM + jA1] = r1;
            }
        }
        publish(&g_fh0[jt * 16]);   // fh0[jt] -> 4(t+1) once all 4 CTAs pass

        // =================== PHASE B ===================
        // mat0 (W_ih1 @ h0(t)):  needs fh0[16 half groups] >= 4(t+1), fh1[jt] >= 4t
        // mat1 (W_hh1 @ h1(t-1)): needs fh1[16 half groups + own] >= 4t
        if (matB == 0) {
            if (tid < 16) wait_ctr(&g_fh0[gB * 16], 4u * (t + 1));
            else if (tid == 16 && t > 0) wait_ctr(&g_fh1[gB * 16], 4u * t);
        } else if (t > 0) {
            if (tid < 17) wait_ctr(&g_fh1[gB * 16], 4u * t);
        }
        __syncthreads();
        {
            const float* hb = (matB ? g_h1T[rp] : g_h0T[wp]) + (size_t)k0B * 64;
            ull acc[4][8];
            #pragma unroll
            for (int j = 0; j < 4; j++)
                #pragma unroll
                for (int p = 0; p < 8; p++) acc[j][p] = 0ull;
            stage_panel(Hs, hb, tid);
            __syncthreads();
            gemm32(WbS, Hs, ksub, jgrp, bgrp, acc);
            __syncthreads();
            stage_panel(Hs, hb + 256 * 64, tid);
            __syncthreads();
            gemm32(WbS + 256 * 32, Hs, ksub, jgrp, bgrp, acc);
            reduce_store(Hs, acc, g_ppB[sub] + (size_t)j0 * 64, tid);
        }
        minibar(&g_mB[jt * 16], 4u * (t + 1));
        {
            float v0 = biasB0 + __ldcg(&g_ppB[0][e0]) + __ldcg(&g_ppB[1][e0])
                              + __ldcg(&g_ppB[2][e0]) + __ldcg(&g_ppB[3][e0]);
            float v1 = biasB1 + __ldcg(&g_ppB[0][e1]) + __ldcg(&g_ppB[1][e1])
                              + __ldcg(&g_ppB[2][e1]) + __ldcg(&g_ppB[3][e1]);
            float r0 = tanhf(v0), r1 = tanhf(v1);
            g_h1T[wp][e0] = r0;
            g_h1T[wp][e1] = r1;
            out[(size_t)t * BH + (size_t)bA0 * HDIM + jA0] = r0;
            out[(size_t)t * BH + (size_t)bA1 * HDIM + jA1] = r1;
            if (t == T_STEPS - 1) {
                out[(size_t)T_STEPS * BH + BH + (size_t)bA0 * HDIM + jA0] = r0;
                out[(size_t)T_STEPS * BH + BH + (size_t)bA1 * HDIM + jA1] = r1;
            }
        }
        publish(&g_fh1[jt * 16]);
    }
}

// =================================================================
// Launch
// =================================================================
extern "C" void kernel_launch(void* const* d_in, const int* in_sizes, int n_in,
                              void* d_out, int out_size)
{
    const float* input = (const float*)d_in[0];
    const float* h_0   = (const float*)d_in[1];
    const float* W_ih0 = (const float*)d_in[2];
    const float* b_ih0 = (const float*)d_in[3];
    const float* W_hh0 = (const float*)d_in[4];
    const float* b_hh0 = (const float*)d_in[5];
    const float* W_ih1 = (const float*)d_in[6];
    const float* b_ih1 = (const float*)d_in[7];
    const float* W_hh1 = (const float*)d_in[8];
    const float* b_hh1 = (const float*)d_in[9];
    float* out = (float*)d_out;

    (void)in_sizes; (void)n_in; (void)out_size;

    const int SMEM_BYTES = (8192 + 16384 + 16384) * 4;   // 163840
    cudaFuncSetAttribute(rnn_persistent,
                         cudaFuncAttributeMaxDynamicSharedMemorySize,
                         SMEM_BYTES);

    // 0) reset sync counters (replay-safe)
    reset_kernel<<<1, 512>>>();

    // 1) X0T = input @ W_ih0^T + b_ih0 + b_hh0
    {
        dim3 grid(HDIM / 128, (T_STEPS * BATCH) / 128);
        precompute_kernel<<<grid, 256>>>(input, W_ih0, b_ih0, b_hh0);
    }

    // 2) persistent recurrence (dataflow flags, no grid barriers in loop)
    rnn_persistent<<<NCTA, NTHR, SMEM_BYTES>>>(h_0, W_hh0, W_ih1, W_hh1,
                                               b_ih1, b_hh1, out);
}